// round 10
// baseline (speedup 1.0000x reference)
#include <cuda_runtime.h>
#include <cstdint>

#define NMAX 1000000
#define EMAX 1000000
#define HDIM 64
#define FIN  19
#define LN_EPS 1e-5f
#define LCAP 262144
#define ECAP 524288

// ---------------- device scratch (zero-initialized; self-cleaned each call) ----
__device__ float g_h[(size_t)NMAX * HDIM];     // h0 (embed) for N0 nodes
__device__ float g_hpA[(size_t)NMAX * HDIM];   // h1 / h3
__device__ float g_hpB[(size_t)NMAX * HDIM];   // h2
__device__ int   g_stamp[NMAX];                // 0=unset, -1=claimed, idx+1 = list pos
__device__ int   g_list[LCAP];
__device__ int   g_nlist;
__device__ int   g_nl[4];                      // g_nl[k] = |N_k|, k=0..3
__device__ int   g_eP[3 * ECAP];               // per-iter edge parent list-index
__device__ int   g_eC[3 * ECAP];               // per-iter edge child node
__device__ int   g_ecnt[3];
__device__ int   g_cntlv[3 * LCAP];            // per-iter child counts by list idx
__device__ float g_sum[(size_t)LCAP * HDIM];   // kept zero between calls (mpnode re-zeroes)
__device__ int   g_is64;
__device__ int   g_done;                       // last-block counter (self-resetting)
__device__ float g_scores[4096];

__device__ __forceinline__ float leaky(float v) { return v > 0.f ? v : 0.01f * v; }

__device__ __forceinline__ float wsum(float v) {
#pragma unroll
    for (int o = 16; o; o >>= 1) v += __shfl_xor_sync(0xffffffffu, v, o);
    return v;
}

__device__ __forceinline__ float* buf_ptr(int sel) {
    return (sel == 0) ? g_h : (sel == 1) ? g_hpA : g_hpB;
}

// ---------------- packed f32x2 helpers ----------------
__device__ __forceinline__ unsigned long long pack2(float lo, float hi) {
    unsigned long long d;
    asm("mov.b64 %0, {%1, %2};" : "=l"(d) : "r"(__float_as_uint(lo)), "r"(__float_as_uint(hi)));
    return d;
}
__device__ __forceinline__ unsigned long long dup2(float v) {
    unsigned long long d;
    unsigned u = __float_as_uint(v);
    asm("mov.b64 %0, {%1, %1};" : "=l"(d) : "r"(u));
    return d;
}
__device__ __forceinline__ void unpack2(unsigned long long v, float& lo, float& hi) {
    unsigned a, b;
    asm("mov.b64 {%0, %1}, %2;" : "=r"(a), "=r"(b) : "l"(v));
    lo = __uint_as_float(a); hi = __uint_as_float(b);
}
__device__ __forceinline__ void fma2(unsigned long long& a, unsigned long long b, unsigned long long c) {
    asm("fma.rn.f32x2 %0, %1, %2, %0;" : "+l"(a) : "l"(b), "l"(c));
}

__device__ __forceinline__ int idx_at(const void* p, int i, int is64, int n) {
    long long v = is64 ? ((const long long*)p)[i] : (long long)((const int*)p)[i];
    unsigned u = (unsigned)v;
    return (u < (unsigned)n) ? (int)u : 0;
}

// ---- mark candidates (single block): dtype detect + dedup-append + snapshot n3 ----
__global__ void mark_cands_kernel(const unsigned* __restrict__ eiw, const void* __restrict__ cand,
                                  int E, int K, int nN) {
    __shared__ int flag;
    if (threadIdx.x == 0) flag = 0;
    __syncthreads();
    int lim = E < 256 ? E : 256;
    if (threadIdx.x < lim && eiw[2 * threadIdx.x + 1] != 0u) flag = 1;
    __syncthreads();
    int is64 = (flag == 0);
    if (threadIdx.x == 0) g_is64 = is64;
    for (int i = threadIdx.x; i < K; i += blockDim.x) {
        int node = idx_at(cand, i, is64, nN);
        if (atomicCAS(&g_stamp[node], 0, -1) == 0) {
            int li = atomicAdd(&g_nlist, 1);
            if (li < LCAP) { g_list[li] = node; __threadfence(); g_stamp[node] = li + 1; }
        }
    }
    __syncthreads();
    if (threadIdx.x == 0) {
        int v = g_nlist;
        g_nl[3] = v < LCAP ? v : LCAP;
    }
}

// ---- edge pass k: collect active edges + counts, expand list; 4 edges/thread;
//      last block snapshots g_nl[k-1] (replaces snap_kernel launches) ----
__global__ void pass_kernel(const void* __restrict__ ei, int E, int nN, int k) {
    int is64 = g_is64;
    int lim = g_nl[k];
    int base = (blockIdx.x * blockDim.x + threadIdx.x) * 4;
#pragma unroll
    for (int j = 0; j < 4; ++j) {
        int e = base + j;
        if (e < E) {
            int p = idx_at(ei, e, is64, nN);
            int s = g_stamp[p];
            if (s > 0 && s <= lim) {
                int c = idx_at(ei, E + e, is64, nN);
                int pi = s - 1;
                atomicAdd(&g_cntlv[(k - 1) * LCAP + pi], 1);
                int ex = atomicAdd(&g_ecnt[k - 1], 1);
                if (ex < ECAP) {
                    g_eP[(k - 1) * ECAP + ex] = pi;
                    g_eC[(k - 1) * ECAP + ex] = c;
                }
                if (g_stamp[c] == 0) {
                    if (atomicCAS(&g_stamp[c], 0, -1) == 0) {
                        int li = atomicAdd(&g_nlist, 1);
                        if (li < LCAP) { g_list[li] = c; __threadfence(); g_stamp[c] = li + 1; }
                    }
                }
            }
        }
    }
    __syncthreads();
    if (threadIdx.x == 0) {
        __threadfence();
        int d = atomicAdd(&g_done, 1);
        if (d == (int)gridDim.x - 1) {
            g_done = 0;
            int v = g_nlist;
            g_nl[k - 1] = v < LCAP ? v : LCAP;
        }
    }
}

// ---------------- embedding for list nodes (packed f32x2, 8 nodes/warp) ------
__global__ __launch_bounds__(128) void embed_list_kernel(
    const float* __restrict__ x, const float* __restrict__ pW, const float* __restrict__ pb,
    const float* __restrict__ eW, const float* __restrict__ eb,
    const float* __restrict__ gamma, const float* __restrict__ beta, int nN)
{
    __shared__ float4 s_pW[10 * 32];
    __shared__ float4 s_eW[2 * 32 * 32];
    __shared__ float4 s_x[4][8][5];
    __shared__ float4 s_h[4][8][16];
    int tid = threadIdx.x;
    for (int i = tid; i < 10 * 32; i += 128) {
        int kp = i >> 5, l = i & 31;
        int k0 = 2 * kp, k1 = 2 * kp + 1;
        float a = (k0 < FIN) ? pW[k0 * 64 + l]      : 0.f;
        float b = (k0 < FIN) ? pW[k0 * 64 + l + 32] : 0.f;
        float c = (k1 < FIN) ? pW[k1 * 64 + l]      : 0.f;
        float d = (k1 < FIN) ? pW[k1 * 64 + l + 32] : 0.f;
        s_pW[i] = make_float4(a, b, c, d);
    }
    for (int i = tid; i < 2 * 32 * 32; i += 128) {
        int li = i >> 10, r = i & 1023, kp = r >> 5, l = r & 31;
        const float* W = eW + li * 4096;
        int k0 = 2 * kp;
        s_eW[i] = make_float4(W[k0 * 64 + l], W[k0 * 64 + l + 32],
                              W[(k0 + 1) * 64 + l], W[(k0 + 1) * 64 + l + 32]);
    }
    __syncthreads();

    int wid = tid >> 5, lane = tid & 31;
    unsigned long long pb2 = pack2(pb[lane], pb[lane + 32]);
    unsigned long long eb2[2];
    float gl[2], ghi[2], bl[2], bh[2];
#pragma unroll
    for (int i2 = 0; i2 < 2; i2++) {
        eb2[i2] = pack2(eb[i2 * 64 + lane], eb[i2 * 64 + lane + 32]);
        gl[i2] = gamma[i2 * 64 + lane];  ghi[i2] = gamma[i2 * 64 + lane + 32];
        bl[i2] = beta[i2 * 64 + lane];   bh[i2] = beta[i2 * 64 + lane + 32];
    }
    float* sxf = (float*)&s_x[wid][0][0];
    float* shf = (float*)&s_h[wid][0][0];

    int n0 = g_nl[0];
    int nG = (n0 + 7) >> 3;
    for (int g = blockIdx.x * 4 + wid; g < nG; g += gridDim.x * 4) {
        int i0 = g << 3;
        int nd = (lane < 8 && i0 + lane < n0) ? g_list[i0 + lane] : -1;
        // broadcast node ids in UNIFORM control flow (shuffles inside ragged loops = UB)
        int ndv[8];
#pragma unroll
        for (int r = 0; r < 8; r++) ndv[r] = __shfl_sync(0xffffffffu, nd, r);
        __syncwarp();
        for (int idx = lane; idx < 8 * FIN; idx += 32) {
            int r = idx / FIN, kk = idx - r * FIN;
            int node = ndv[r];
            sxf[r * 20 + kk] = (node >= 0) ? x[(size_t)node * FIN + kk] : 0.f;
        }
        if (lane < 8) sxf[lane * 20 + 19] = 0.f;
        __syncwarp();

        unsigned long long acc[8];
#pragma unroll
        for (int r = 0; r < 8; r++) acc[r] = pb2;
#pragma unroll
        for (int kq = 0; kq < 5; ++kq) {
            ulonglong2 w0 = *(const ulonglong2*)&s_pW[(2 * kq) * 32 + lane];
            ulonglong2 w1 = *(const ulonglong2*)&s_pW[(2 * kq + 1) * 32 + lane];
#pragma unroll
            for (int r = 0; r < 8; r++) {
                float4 xv = s_x[wid][r][kq];
                fma2(acc[r], w0.x, dup2(xv.x));
                fma2(acc[r], w0.y, dup2(xv.y));
                fma2(acc[r], w1.x, dup2(xv.z));
                fma2(acc[r], w1.y, dup2(xv.w));
            }
        }
        float hl[8], hh[8];
#pragma unroll
        for (int r = 0; r < 8; r++) {
            float a, b; unpack2(acc[r], a, b);
            hl[r] = leaky(a); hh[r] = leaky(b);
        }

#pragma unroll
        for (int li = 0; li < 2; ++li) {
#pragma unroll
            for (int r = 0; r < 8; r++) { shf[r * 64 + lane] = hl[r]; shf[r * 64 + lane + 32] = hh[r]; }
            __syncwarp();
#pragma unroll
            for (int r = 0; r < 8; r++) acc[r] = eb2[li];
#pragma unroll
            for (int kq = 0; kq < 16; ++kq) {
                ulonglong2 w0 = *(const ulonglong2*)&s_eW[li * 1024 + (2 * kq) * 32 + lane];
                ulonglong2 w1 = *(const ulonglong2*)&s_eW[li * 1024 + (2 * kq + 1) * 32 + lane];
#pragma unroll
                for (int r = 0; r < 8; r++) {
                    float4 hv = s_h[wid][r][kq];
                    fma2(acc[r], w0.x, dup2(hv.x));
                    fma2(acc[r], w0.y, dup2(hv.y));
                    fma2(acc[r], w1.x, dup2(hv.z));
                    fma2(acc[r], w1.y, dup2(hv.w));
                }
            }
#pragma unroll
            for (int r = 0; r < 8; r++) {
                float tl, th; unpack2(acc[r], tl, th);
                float ul = hl[r] + leaky(tl);
                float uh = hh[r] + leaky(th);
                float s1 = wsum(ul + uh);
                float s2 = wsum(ul * ul + uh * uh);
                float mu = s1 * (1.f / 64.f);
                float var = s2 * (1.f / 64.f) - mu * mu;
                float inv = rsqrtf(var + LN_EPS);
                hl[r] = (ul - mu) * inv * gl[li] + bl[li];
                hh[r] = (uh - mu) * inv * ghi[li] + bh[li];
            }
            __syncwarp();
        }
#pragma unroll
        for (int r = 0; r < 8; r++) {
            if (ndv[r] >= 0) {
                g_h[(size_t)ndv[r] * 64 + lane] = hl[r];
                g_h[(size_t)ndv[r] * 64 + lane + 32] = hh[r];
            }
        }
    }
}

// ---------------- edge-parallel accumulate (g_sum pre-zeroed invariant) ------
__global__ void accum_kernel(int prevSel, int k) {
    const float* prev = buf_ptr(prevSel);
    int lane = threadIdx.x & 31;
    int w = (blockIdx.x * blockDim.x + threadIdx.x) >> 5;
    int nw = (gridDim.x * blockDim.x) >> 5;
    int ne = g_ecnt[k - 1]; if (ne > ECAP) ne = ECAP;
    for (int e = w; e < ne; e += nw) {
        int pi = g_eP[(k - 1) * ECAP + e];
        int c  = g_eC[(k - 1) * ECAP + e];
        const float* hr = prev + (size_t)c * 64;
        atomicAdd(&g_sum[(size_t)pi * 64 + lane], hr[lane]);
        atomicAdd(&g_sum[(size_t)pi * 64 + lane + 32], hr[lane + 32]);
    }
}

// ------- node-parallel MP update (mean -> MLP -> residual); re-zeroes g_sum ----
__global__ __launch_bounds__(256) void mpnode_kernel(
    const float* __restrict__ W1g, const float* __restrict__ b1g,
    const float* __restrict__ W2g, const float* __restrict__ b2g,
    int prevSel, int outSel, int k)
{
    __shared__ float4 s_W1[1024];
    __shared__ float4 s_W2[1024];
    __shared__ float4 s_hq[8][4][16];
    int tid = threadIdx.x;
    for (int i = tid; i < 1024; i += 256) {
        int kp = i >> 5, l = i & 31; int k0 = kp * 2;
        s_W1[i] = make_float4(W1g[k0 * 64 + l], W1g[k0 * 64 + l + 32],
                              W1g[(k0 + 1) * 64 + l], W1g[(k0 + 1) * 64 + l + 32]);
        s_W2[i] = make_float4(W2g[k0 * 64 + l], W2g[k0 * 64 + l + 32],
                              W2g[(k0 + 1) * 64 + l], W2g[(k0 + 1) * 64 + l + 32]);
    }
    __syncthreads();
    const float* prev = buf_ptr(prevSel);
    float* out = buf_ptr(outSel);
    int wid = tid >> 5, lane = tid & 31;
    float b1l = b1g[lane], b1h = b1g[lane + 32];
    float b2l = b2g[lane], b2h = b2g[lane + 32];
    float* shf = (float*)&s_hq[wid][0][0];
    int n = g_nl[k];
    int cb = (k - 1) * LCAP;
    for (int i0 = (blockIdx.x * 8 + wid) * 4; i0 < n; i0 += gridDim.x * 32) {
        int nodes[4], ccs[4];
        __syncwarp();
#pragma unroll
        for (int r = 0; r < 4; r++) {
            int ix = i0 + r;
            float ml = 0.f, mh = 0.f;
            if (ix < n) {
                nodes[r] = g_list[ix];
                ccs[r] = g_cntlv[cb + ix];
                if (ccs[r] > 0) {
                    float inv = 1.f / (float)ccs[r];
                    ml = g_sum[(size_t)ix * 64 + lane] * inv;
                    mh = g_sum[(size_t)ix * 64 + lane + 32] * inv;
                }
                // restore the all-zero g_sum invariant for the next iteration/call
                g_sum[(size_t)ix * 64 + lane] = 0.f;
                g_sum[(size_t)ix * 64 + lane + 32] = 0.f;
            } else { nodes[r] = -1; ccs[r] = 0; }
            shf[r * 64 + lane] = ml;
            shf[r * 64 + lane + 32] = mh;
        }
        __syncwarp();
        float tl[4], th[4];
#pragma unroll
        for (int r = 0; r < 4; r++) { tl[r] = b1l; th[r] = b1h; }
#pragma unroll
        for (int kq = 0; kq < 16; ++kq) {
            float4 w0 = s_W1[(2 * kq) * 32 + lane];
            float4 w1 = s_W1[(2 * kq + 1) * 32 + lane];
#pragma unroll
            for (int r = 0; r < 4; r++) {
                float4 hv = s_hq[wid][r][kq];
                tl[r] += hv.x * w0.x + hv.y * w0.z + hv.z * w1.x + hv.w * w1.z;
                th[r] += hv.x * w0.y + hv.y * w0.w + hv.z * w1.y + hv.w * w1.w;
            }
        }
        __syncwarp();
#pragma unroll
        for (int r = 0; r < 4; r++) {
            shf[r * 64 + lane] = leaky(tl[r]);
            shf[r * 64 + lane + 32] = leaky(th[r]);
        }
        __syncwarp();
        float ol[4], oh[4];
#pragma unroll
        for (int r = 0; r < 4; r++) { ol[r] = b2l; oh[r] = b2h; }
#pragma unroll
        for (int kq = 0; kq < 16; ++kq) {
            float4 w0 = s_W2[(2 * kq) * 32 + lane];
            float4 w1 = s_W2[(2 * kq + 1) * 32 + lane];
#pragma unroll
            for (int r = 0; r < 4; r++) {
                float4 hv = s_hq[wid][r][kq];
                ol[r] += hv.x * w0.x + hv.y * w0.z + hv.z * w1.x + hv.w * w1.z;
                oh[r] += hv.x * w0.y + hv.y * w0.w + hv.z * w1.y + hv.w * w1.w;
            }
        }
#pragma unroll
        for (int r = 0; r < 4; r++) {
            if (nodes[r] >= 0) {
                const float* pv = prev + (size_t)nodes[r] * 64;
                float* ov = out + (size_t)nodes[r] * 64;
                float dl = (ccs[r] > 0) ? ol[r] : 0.f;
                float dh = (ccs[r] > 0) ? oh[r] : 0.f;
                ov[lane]      = pv[lane] + dl;
                ov[lane + 32] = pv[lane + 32] + dh;
            }
        }
    }
}

// ---------------- score head (parallel) + softmax ----------------
__global__ __launch_bounds__(256) void scores_kernel(
    const void* __restrict__ cand,
    const float* __restrict__ W1g, const float* __restrict__ b1g,
    const float* __restrict__ W2g, const float* __restrict__ b2g,
    int K, int nN)
{
    __shared__ float4 s_W1[1024];
    __shared__ float4 s_hq[8][4][16];
    int tid = threadIdx.x;
    int is64 = g_is64;
    for (int i = tid; i < 1024; i += 256) {
        int kp = i >> 5, l = i & 31; int k0 = kp * 2;
        s_W1[i] = make_float4(W1g[k0 * 64 + l], W1g[k0 * 64 + l + 32],
                              W1g[(k0 + 1) * 64 + l], W1g[(k0 + 1) * 64 + l + 32]);
    }
    __syncthreads();
    int wid = tid >> 5, lane = tid & 31;
    float b1l = b1g[lane], b1h = b1g[lane + 32];
    float w2l = W2g[lane], w2h = W2g[lane + 32];
    float b2s = b2g[0];
    float* shf = (float*)&s_hq[wid][0][0];
    int nQ = (K + 3) >> 2;
    int q = blockIdx.x * 8 + wid;
    if (q >= nQ) return;
    int c0 = q << 2;
#pragma unroll
    for (int r = 0; r < 4; r++) {
        if (c0 + r < K) {
            int node = idx_at(cand, c0 + r, is64, nN);
            const float* hr = g_hpA + (size_t)node * 64;   // h3 lives in A
            shf[r * 64 + lane] = hr[lane];
            shf[r * 64 + lane + 32] = hr[lane + 32];
        } else {
            shf[r * 64 + lane] = 0.f;
            shf[r * 64 + lane + 32] = 0.f;
        }
    }
    __syncwarp();
    float tl[4], th[4];
#pragma unroll
    for (int r = 0; r < 4; r++) { tl[r] = b1l; th[r] = b1h; }
#pragma unroll
    for (int kq = 0; kq < 16; ++kq) {
        float4 w0 = s_W1[(2 * kq) * 32 + lane];
        float4 w1 = s_W1[(2 * kq + 1) * 32 + lane];
#pragma unroll
        for (int r = 0; r < 4; r++) {
            float4 hv = s_hq[wid][r][kq];
            tl[r] += hv.x * w0.x + hv.y * w0.z + hv.z * w1.x + hv.w * w1.z;
            th[r] += hv.x * w0.y + hv.y * w0.w + hv.z * w1.y + hv.w * w1.w;
        }
    }
#pragma unroll
    for (int r = 0; r < 4; r++) {
        float s = leaky(tl[r]) * w2l + leaky(th[r]) * w2h;
        s = wsum(s) + b2s;
        if (lane == 0 && c0 + r < K) g_scores[c0 + r] = s;
    }
}

__global__ __launch_bounds__(256) void softmax_kernel(float* __restrict__ out, int K) {
    __shared__ float s_red[256];
    int tid = threadIdx.x;
    float m = -3.4e38f;
    for (int i = tid; i < K; i += 256) m = fmaxf(m, g_scores[i]);
    s_red[tid] = m; __syncthreads();
    for (int o = 128; o; o >>= 1) { if (tid < o) s_red[tid] = fmaxf(s_red[tid], s_red[tid + o]); __syncthreads(); }
    m = s_red[0];
    __syncthreads();
    float sum = 0.f;
    for (int i = tid; i < K; i += 256) sum += expf(g_scores[i] - m);
    s_red[tid] = sum; __syncthreads();
    for (int o = 128; o; o >>= 1) { if (tid < o) s_red[tid] += s_red[tid + o]; __syncthreads(); }
    float invT = 1.f / s_red[0];
    for (int i = tid; i < K; i += 256) out[i] = expf(g_scores[i] - m) * invT;
}

// ---- cleanup: restore pristine global state (replaces the 1M-word reset) ----
__global__ void cleanup_kernel() {
    int n0 = g_nl[0];
    int stride = gridDim.x * blockDim.x;
    for (int i = blockIdx.x * blockDim.x + threadIdx.x; i < n0; i += stride) {
        g_stamp[g_list[i]] = 0;
        g_cntlv[i] = 0;
        g_cntlv[LCAP + i] = 0;
        g_cntlv[2 * LCAP + i] = 0;
    }
    if (blockIdx.x == 0 && threadIdx.x == 0) {
        g_nlist = 0;
        g_ecnt[0] = g_ecnt[1] = g_ecnt[2] = 0;
        g_nl[0] = g_nl[1] = g_nl[2] = g_nl[3] = 0;
    }
}

// ---------------- launch ----------------
extern "C" void kernel_launch(void* const* d_in, const int* in_sizes, int n_in,
                              void* d_out, int out_size) {
    const float* x     = (const float*)d_in[0];
    const void*  ei    = d_in[1];
    const void*  cand  = d_in[2];
    const float* pW    = (const float*)d_in[3];
    const float* pb    = (const float*)d_in[4];
    const float* eW    = (const float*)d_in[5];
    const float* eb    = (const float*)d_in[6];
    const float* gamma = (const float*)d_in[7];
    const float* beta  = (const float*)d_in[8];
    const float* sW1   = (const float*)d_in[9];
    const float* sb1   = (const float*)d_in[10];
    const float* sW2   = (const float*)d_in[11];
    const float* sb2   = (const float*)d_in[12];
    const float* hW1   = (const float*)d_in[13];
    const float* hb1   = (const float*)d_in[14];
    const float* hW2   = (const float*)d_in[15];
    const float* hb2   = (const float*)d_in[16];

    int nN = in_sizes[0] / FIN;
    int E  = in_sizes[1] / 2;
    int K  = in_sizes[2];
    int pBlocks = (E + 1023) / 1024;   // 4 edges per thread

    mark_cands_kernel<<<1, 512>>>((const unsigned*)ei, cand, E, K, nN);   // 1
    pass_kernel<<<pBlocks, 256>>>(ei, E, nN, 3);                          // 2
    pass_kernel<<<pBlocks, 256>>>(ei, E, nN, 2);                          // 3
    pass_kernel<<<pBlocks, 256>>>(ei, E, nN, 1);                          // 4 <- profiled
    embed_list_kernel<<<128, 128>>>(x, pW, pb, eW, eb, gamma, beta, nN);  // 5

    // iter 1: g_h(0) -> A(1) ; iter 2: A(1) -> B(2) ; iter 3: B(2) -> A(1)
    const int prevSel[3] = { 0, 1, 2 };
    const int outSel[3]  = { 1, 2, 1 };
    for (int it = 0; it < 3; ++it) {
        int k = it + 1;
        accum_kernel<<<32, 256>>>(prevSel[it], k);
        mpnode_kernel<<<32, 256>>>(sW1 + it * 4096, sb1 + it * 64,
                                   sW2 + it * 4096, sb2 + it * 64,
                                   prevSel[it], outSel[it], k);
    }

    int sBlocks = ((K + 3) / 4 + 7) / 8;
    scores_kernel<<<sBlocks, 256>>>(cand, hW1, hb1, hW2, hb2, K, nN);
    softmax_kernel<<<1, 256>>>((float*)d_out, K);
    cleanup_kernel<<<16, 256>>>();
}

// round 11
// speedup vs baseline: 1.0030x; 1.0030x over previous
#include <cuda_runtime.h>
#include <cstdint>

#define NMAX 1000000
#define EMAX 1000000
#define HDIM 64
#define FIN  19
#define LN_EPS 1e-5f
#define LCAP 262144
#define ECAP 524288

// ---------------- device scratch (zero-initialized; self-cleaned each call) ----
__device__ float g_h[(size_t)NMAX * HDIM];     // h0 (embed) for N0 nodes
__device__ float g_hpA[(size_t)NMAX * HDIM];   // h1 / h3
__device__ float g_hpB[(size_t)NMAX * HDIM];   // h2
__device__ int   g_stamp[NMAX];                // 0=unset, -1=claimed, idx+1 = list pos
__device__ int   g_p32[EMAX];                  // compacted int32 parent per edge (pass3)
__device__ int   g_list[LCAP];
__device__ int   g_nlist;
__device__ int   g_nl[4];                      // g_nl[k] = |N_k|, k=0..3
__device__ int   g_eP[3 * ECAP];               // per-iter edge parent list-index
__device__ int   g_eC[3 * ECAP];               // per-iter edge child node
__device__ int   g_ecnt[3];
__device__ int   g_cntlv[3 * LCAP];            // per-iter child counts by list idx
__device__ float g_sum[(size_t)LCAP * HDIM];   // all-zero invariant between calls
__device__ int   g_is64;
__device__ int   g_done;                       // last-block counter (self-resetting)
__device__ int   g_bar_count;                  // grid barrier (self-resetting)
__device__ int   g_bar_sense;                  // ends at 0 every call (even # barriers)
__device__ float g_scores[4096];

__device__ __forceinline__ float leaky(float v) { return v > 0.f ? v : 0.01f * v; }

__device__ __forceinline__ float wsum(float v) {
#pragma unroll
    for (int o = 16; o; o >>= 1) v += __shfl_xor_sync(0xffffffffu, v, o);
    return v;
}

__device__ __forceinline__ float* buf_ptr(int sel) {
    return (sel == 0) ? g_h : (sel == 1) ? g_hpA : g_hpB;
}

// ---------------- packed f32x2 helpers ----------------
__device__ __forceinline__ unsigned long long pack2(float lo, float hi) {
    unsigned long long d;
    asm("mov.b64 %0, {%1, %2};" : "=l"(d) : "r"(__float_as_uint(lo)), "r"(__float_as_uint(hi)));
    return d;
}
__device__ __forceinline__ unsigned long long dup2(float v) {
    unsigned long long d;
    unsigned u = __float_as_uint(v);
    asm("mov.b64 %0, {%1, %1};" : "=l"(d) : "r"(u));
    return d;
}
__device__ __forceinline__ void unpack2(unsigned long long v, float& lo, float& hi) {
    unsigned a, b;
    asm("mov.b64 {%0, %1}, %2;" : "=r"(a), "=r"(b) : "l"(v));
    lo = __uint_as_float(a); hi = __uint_as_float(b);
}
__device__ __forceinline__ void fma2(unsigned long long& a, unsigned long long b, unsigned long long c) {
    asm("fma.rn.f32x2 %0, %1, %2, %0;" : "+l"(a) : "l"(b), "l"(c));
}

__device__ __forceinline__ int idx_at(const void* p, int i, int is64, int n) {
    long long v = is64 ? ((const long long*)p)[i] : (long long)((const int*)p)[i];
    unsigned u = (unsigned)v;
    return (u < (unsigned)n) ? (int)u : 0;
}

// sense-reversing grid barrier (blocks must be co-resident; callers use <=64 blocks)
__device__ __forceinline__ void grid_barrier(int* s_sense) {
    __syncthreads();
    if (threadIdx.x == 0) {
        int s = *s_sense ^ 1;
        *s_sense = s;
        __threadfence();
        int v = atomicAdd(&g_bar_count, 1);
        if (v == (int)gridDim.x - 1) {
            g_bar_count = 0;
            __threadfence();
            atomicExch(&g_bar_sense, s);
        } else {
            while (atomicAdd(&g_bar_sense, 0) != s) {}
        }
        __threadfence();
    }
    __syncthreads();
}

// ---- mark candidates (single block): dtype detect + dedup-append + snapshot n3 ----
__global__ void mark_cands_kernel(const unsigned* __restrict__ eiw, const void* __restrict__ cand,
                                  int E, int K, int nN) {
    __shared__ int flag;
    if (threadIdx.x == 0) flag = 0;
    __syncthreads();
    int lim = E < 256 ? E : 256;
    if (threadIdx.x < lim && eiw[2 * threadIdx.x + 1] != 0u) flag = 1;
    __syncthreads();
    int is64 = (flag == 0);
    if (threadIdx.x == 0) g_is64 = is64;
    for (int i = threadIdx.x; i < K; i += blockDim.x) {
        int node = idx_at(cand, i, is64, nN);
        if (atomicCAS(&g_stamp[node], 0, -1) == 0) {
            int li = atomicAdd(&g_nlist, 1);
            if (li < LCAP) { g_list[li] = node; __threadfence(); g_stamp[node] = li + 1; }
        }
    }
    __syncthreads();
    if (threadIdx.x == 0) {
        int v = g_nlist;
        g_nl[3] = v < LCAP ? v : LCAP;
    }
}

// ---- shared hit-processing for edge passes ----
__device__ __forceinline__ void process_hit(int k, int pi, int c) {
    atomicAdd(&g_cntlv[(k - 1) * LCAP + pi], 1);
    int ex = atomicAdd(&g_ecnt[k - 1], 1);
    if (ex < ECAP) {
        g_eP[(k - 1) * ECAP + ex] = pi;
        g_eC[(k - 1) * ECAP + ex] = c;
    }
    if (g_stamp[c] == 0) {
        if (atomicCAS(&g_stamp[c], 0, -1) == 0) {
            int li = atomicAdd(&g_nlist, 1);
            if (li < LCAP) { g_list[li] = c; __threadfence(); g_stamp[c] = li + 1; }
        }
    }
}

__device__ __forceinline__ void pass_snapshot(int k) {
    __syncthreads();
    if (threadIdx.x == 0) {
        __threadfence();
        int d = atomicAdd(&g_done, 1);
        if (d == (int)gridDim.x - 1) {
            g_done = 0;
            int v = g_nlist;
            g_nl[k - 1] = v < LCAP ? v : LCAP;
        }
    }
}

// ---- pass 3: batched (8 edges/thread, column-major) + int32 parent compaction ----
__global__ void pass3_kernel(const void* __restrict__ ei, int E, int nN) {
    int is64 = g_is64;
    int lim = g_nl[3];
    int gid = blockIdx.x * blockDim.x + threadIdx.x;
    int stride = gridDim.x * blockDim.x;
    int pv[8], ev[8];
#pragma unroll
    for (int j = 0; j < 8; ++j) {
        int e = gid + j * stride;
        ev[j] = e;
        pv[j] = (e < E) ? idx_at(ei, e, is64, nN) : 0;
    }
#pragma unroll
    for (int j = 0; j < 8; ++j)
        if (ev[j] < E) g_p32[ev[j]] = pv[j];
    int sv[8];
#pragma unroll
    for (int j = 0; j < 8; ++j) sv[j] = g_stamp[pv[j]];
#pragma unroll
    for (int j = 0; j < 8; ++j) {
        if (ev[j] < E) {
            int s = sv[j];
            if (s > 0 && s <= lim) {
                int c = idx_at(ei, E + ev[j], is64, nN);
                process_hit(3, s - 1, c);
            }
        }
    }
    pass_snapshot(3);
}

// ---- passes 2 and 1: read compacted int32 parents ----
__global__ void passc_kernel(const void* __restrict__ ei, int E, int nN, int k) {
    int is64 = g_is64;
    int lim = g_nl[k];
    int gid = blockIdx.x * blockDim.x + threadIdx.x;
    int stride = gridDim.x * blockDim.x;
    int pv[8], ev[8];
#pragma unroll
    for (int j = 0; j < 8; ++j) {
        int e = gid + j * stride;
        ev[j] = e;
        pv[j] = (e < E) ? g_p32[e] : 0;
    }
    int sv[8];
#pragma unroll
    for (int j = 0; j < 8; ++j) sv[j] = g_stamp[pv[j]];
#pragma unroll
    for (int j = 0; j < 8; ++j) {
        if (ev[j] < E) {
            int s = sv[j];
            if (s > 0 && s <= lim) {
                int c = idx_at(ei, E + ev[j], is64, nN);
                process_hit(k, s - 1, c);
            }
        }
    }
    pass_snapshot(k);
}

// ---------------- embedding for list nodes (packed f32x2, 8 nodes/warp) ------
__global__ __launch_bounds__(128) void embed_list_kernel(
    const float* __restrict__ x, const float* __restrict__ pW, const float* __restrict__ pb,
    const float* __restrict__ eW, const float* __restrict__ eb,
    const float* __restrict__ gamma, const float* __restrict__ beta, int nN)
{
    __shared__ float4 s_pW[10 * 32];
    __shared__ float4 s_eW[2 * 32 * 32];
    __shared__ float4 s_x[4][8][5];
    __shared__ float4 s_h[4][8][16];
    int tid = threadIdx.x;
    for (int i = tid; i < 10 * 32; i += 128) {
        int kp = i >> 5, l = i & 31;
        int k0 = 2 * kp, k1 = 2 * kp + 1;
        float a = (k0 < FIN) ? pW[k0 * 64 + l]      : 0.f;
        float b = (k0 < FIN) ? pW[k0 * 64 + l + 32] : 0.f;
        float c = (k1 < FIN) ? pW[k1 * 64 + l]      : 0.f;
        float d = (k1 < FIN) ? pW[k1 * 64 + l + 32] : 0.f;
        s_pW[i] = make_float4(a, b, c, d);
    }
    for (int i = tid; i < 2 * 32 * 32; i += 128) {
        int li = i >> 10, r = i & 1023, kp = r >> 5, l = r & 31;
        const float* W = eW + li * 4096;
        int k0 = 2 * kp;
        s_eW[i] = make_float4(W[k0 * 64 + l], W[k0 * 64 + l + 32],
                              W[(k0 + 1) * 64 + l], W[(k0 + 1) * 64 + l + 32]);
    }
    __syncthreads();

    int wid = tid >> 5, lane = tid & 31;
    unsigned long long pb2 = pack2(pb[lane], pb[lane + 32]);
    unsigned long long eb2[2];
    float gl[2], ghi[2], bl[2], bh[2];
#pragma unroll
    for (int i2 = 0; i2 < 2; i2++) {
        eb2[i2] = pack2(eb[i2 * 64 + lane], eb[i2 * 64 + lane + 32]);
        gl[i2] = gamma[i2 * 64 + lane];  ghi[i2] = gamma[i2 * 64 + lane + 32];
        bl[i2] = beta[i2 * 64 + lane];   bh[i2] = beta[i2 * 64 + lane + 32];
    }
    float* sxf = (float*)&s_x[wid][0][0];
    float* shf = (float*)&s_h[wid][0][0];

    int n0 = g_nl[0];
    int nG = (n0 + 7) >> 3;
    for (int g = blockIdx.x * 4 + wid; g < nG; g += gridDim.x * 4) {
        int i0 = g << 3;
        int nd = (lane < 8 && i0 + lane < n0) ? g_list[i0 + lane] : -1;
        // broadcast node ids in UNIFORM control flow (shuffles inside ragged loops = UB)
        int ndv[8];
#pragma unroll
        for (int r = 0; r < 8; r++) ndv[r] = __shfl_sync(0xffffffffu, nd, r);
        __syncwarp();
        for (int idx = lane; idx < 8 * FIN; idx += 32) {
            int r = idx / FIN, kk = idx - r * FIN;
            int node = ndv[r];
            sxf[r * 20 + kk] = (node >= 0) ? x[(size_t)node * FIN + kk] : 0.f;
        }
        if (lane < 8) sxf[lane * 20 + 19] = 0.f;
        __syncwarp();

        unsigned long long acc[8];
#pragma unroll
        for (int r = 0; r < 8; r++) acc[r] = pb2;
#pragma unroll
        for (int kq = 0; kq < 5; ++kq) {
            ulonglong2 w0 = *(const ulonglong2*)&s_pW[(2 * kq) * 32 + lane];
            ulonglong2 w1 = *(const ulonglong2*)&s_pW[(2 * kq + 1) * 32 + lane];
#pragma unroll
            for (int r = 0; r < 8; r++) {
                float4 xv = s_x[wid][r][kq];
                fma2(acc[r], w0.x, dup2(xv.x));
                fma2(acc[r], w0.y, dup2(xv.y));
                fma2(acc[r], w1.x, dup2(xv.z));
                fma2(acc[r], w1.y, dup2(xv.w));
            }
        }
        float hl[8], hh[8];
#pragma unroll
        for (int r = 0; r < 8; r++) {
            float a, b; unpack2(acc[r], a, b);
            hl[r] = leaky(a); hh[r] = leaky(b);
        }

#pragma unroll
        for (int li = 0; li < 2; ++li) {
#pragma unroll
            for (int r = 0; r < 8; r++) { shf[r * 64 + lane] = hl[r]; shf[r * 64 + lane + 32] = hh[r]; }
            __syncwarp();
#pragma unroll
            for (int r = 0; r < 8; r++) acc[r] = eb2[li];
#pragma unroll
            for (int kq = 0; kq < 16; ++kq) {
                ulonglong2 w0 = *(const ulonglong2*)&s_eW[li * 1024 + (2 * kq) * 32 + lane];
                ulonglong2 w1 = *(const ulonglong2*)&s_eW[li * 1024 + (2 * kq + 1) * 32 + lane];
#pragma unroll
                for (int r = 0; r < 8; r++) {
                    float4 hv = s_h[wid][r][kq];
                    fma2(acc[r], w0.x, dup2(hv.x));
                    fma2(acc[r], w0.y, dup2(hv.y));
                    fma2(acc[r], w1.x, dup2(hv.z));
                    fma2(acc[r], w1.y, dup2(hv.w));
                }
            }
#pragma unroll
            for (int r = 0; r < 8; r++) {
                float tl, th; unpack2(acc[r], tl, th);
                float ul = hl[r] + leaky(tl);
                float uh = hh[r] + leaky(th);
                float s1 = wsum(ul + uh);
                float s2 = wsum(ul * ul + uh * uh);
                float mu = s1 * (1.f / 64.f);
                float var = s2 * (1.f / 64.f) - mu * mu;
                float inv = rsqrtf(var + LN_EPS);
                hl[r] = (ul - mu) * inv * gl[li] + bl[li];
                hh[r] = (uh - mu) * inv * ghi[li] + bh[li];
            }
            __syncwarp();
        }
#pragma unroll
        for (int r = 0; r < 8; r++) {
            if (ndv[r] >= 0) {
                g_h[(size_t)ndv[r] * 64 + lane] = hl[r];
                g_h[(size_t)ndv[r] * 64 + lane + 32] = hh[r];
            }
        }
    }
}

// ------- fused message passing: 3x (accum + mpnode) in ONE persistent kernel ----
// Cross-phase global traffic uses .cg (L2) ops; grid barriers between phases.
__global__ __launch_bounds__(256) void mp_fused_kernel(
    const float* __restrict__ sW1, const float* __restrict__ sb1,
    const float* __restrict__ sW2, const float* __restrict__ sb2)
{
    __shared__ float4 s_W1[1024];
    __shared__ float4 s_W2[1024];
    __shared__ float4 s_hq[8][4][16];
    __shared__ int s_sense;
    int tid = threadIdx.x;
    int wid = tid >> 5, lane = tid & 31;
    if (tid == 0) s_sense = 0;
    __syncthreads();

    const int prevSelA[3] = { 0, 1, 2 };
    const int outSelA[3]  = { 1, 2, 1 };

    for (int it = 0; it < 3; ++it) {
        int k = it + 1;
        const float* W1g = sW1 + it * 4096;
        const float* b1g = sb1 + it * 64;
        const float* W2g = sW2 + it * 4096;
        const float* b2g = sb2 + it * 64;
        // weight load (previous iteration's use finished via grid barrier)
        for (int i = tid; i < 1024; i += 256) {
            int kp = i >> 5, l = i & 31; int k0 = kp * 2;
            s_W1[i] = make_float4(W1g[k0 * 64 + l], W1g[k0 * 64 + l + 32],
                                  W1g[(k0 + 1) * 64 + l], W1g[(k0 + 1) * 64 + l + 32]);
            s_W2[i] = make_float4(W2g[k0 * 64 + l], W2g[k0 * 64 + l + 32],
                                  W2g[(k0 + 1) * 64 + l], W2g[(k0 + 1) * 64 + l + 32]);
        }
        const float* prev = buf_ptr(prevSelA[it]);
        float* out = buf_ptr(outSelA[it]);
        __syncthreads();

        // ---- accum phase: warp per active edge ----
        {
            int ne = g_ecnt[k - 1]; if (ne > ECAP) ne = ECAP;
            int w = (blockIdx.x * 256 + tid) >> 5;
            int nw = (gridDim.x * 256) >> 5;
            for (int e = w; e < ne; e += nw) {
                int pi = g_eP[(k - 1) * ECAP + e];
                int c  = g_eC[(k - 1) * ECAP + e];
                const float* hr = prev + (size_t)c * 64;
                atomicAdd(&g_sum[(size_t)pi * 64 + lane], __ldcg(hr + lane));
                atomicAdd(&g_sum[(size_t)pi * 64 + lane + 32], __ldcg(hr + lane + 32));
            }
        }
        grid_barrier(&s_sense);

        // ---- mpnode phase: mean -> MLP -> residual; re-zero g_sum rows ----
        {
            float b1l = b1g[lane], b1h = b1g[lane + 32];
            float b2l = b2g[lane], b2h = b2g[lane + 32];
            float* shf = (float*)&s_hq[wid][0][0];
            int n = g_nl[k];
            int cb = (k - 1) * LCAP;
            for (int i0 = (blockIdx.x * 8 + wid) * 4; i0 < n; i0 += gridDim.x * 32) {
                int nodes[4], ccs[4];
                __syncwarp();
#pragma unroll
                for (int r = 0; r < 4; r++) {
                    int ix = i0 + r;
                    float ml = 0.f, mh = 0.f;
                    if (ix < n) {
                        nodes[r] = g_list[ix];
                        ccs[r] = g_cntlv[cb + ix];
                        if (ccs[r] > 0) {
                            float inv = 1.f / (float)ccs[r];
                            ml = __ldcg(&g_sum[(size_t)ix * 64 + lane]) * inv;
                            mh = __ldcg(&g_sum[(size_t)ix * 64 + lane + 32]) * inv;
                        }
                        __stcg(&g_sum[(size_t)ix * 64 + lane], 0.f);
                        __stcg(&g_sum[(size_t)ix * 64 + lane + 32], 0.f);
                    } else { nodes[r] = -1; ccs[r] = 0; }
                    shf[r * 64 + lane] = ml;
                    shf[r * 64 + lane + 32] = mh;
                }
                __syncwarp();
                float tl[4], th[4];
#pragma unroll
                for (int r = 0; r < 4; r++) { tl[r] = b1l; th[r] = b1h; }
#pragma unroll
                for (int kq = 0; kq < 16; ++kq) {
                    float4 w0 = s_W1[(2 * kq) * 32 + lane];
                    float4 w1 = s_W1[(2 * kq + 1) * 32 + lane];
#pragma unroll
                    for (int r = 0; r < 4; r++) {
                        float4 hv = s_hq[wid][r][kq];
                        tl[r] += hv.x * w0.x + hv.y * w0.z + hv.z * w1.x + hv.w * w1.z;
                        th[r] += hv.x * w0.y + hv.y * w0.w + hv.z * w1.y + hv.w * w1.w;
                    }
                }
                __syncwarp();
#pragma unroll
                for (int r = 0; r < 4; r++) {
                    shf[r * 64 + lane] = leaky(tl[r]);
                    shf[r * 64 + lane + 32] = leaky(th[r]);
                }
                __syncwarp();
                float ol[4], oh[4];
#pragma unroll
                for (int r = 0; r < 4; r++) { ol[r] = b2l; oh[r] = b2h; }
#pragma unroll
                for (int kq = 0; kq < 16; ++kq) {
                    float4 w0 = s_W2[(2 * kq) * 32 + lane];
                    float4 w1 = s_W2[(2 * kq + 1) * 32 + lane];
#pragma unroll
                    for (int r = 0; r < 4; r++) {
                        float4 hv = s_hq[wid][r][kq];
                        ol[r] += hv.x * w0.x + hv.y * w0.z + hv.z * w1.x + hv.w * w1.z;
                        oh[r] += hv.x * w0.y + hv.y * w0.w + hv.z * w1.y + hv.w * w1.w;
                    }
                }
#pragma unroll
                for (int r = 0; r < 4; r++) {
                    if (nodes[r] >= 0) {
                        const float* pv = prev + (size_t)nodes[r] * 64;
                        float* ov = out + (size_t)nodes[r] * 64;
                        float dl = (ccs[r] > 0) ? ol[r] : 0.f;
                        float dh = (ccs[r] > 0) ? oh[r] : 0.f;
                        __stcg(ov + lane,      __ldcg(pv + lane) + dl);
                        __stcg(ov + lane + 32, __ldcg(pv + lane + 32) + dh);
                    }
                }
            }
        }
        grid_barrier(&s_sense);
    }
}

// ---------------- score head (parallel) ----------------
__global__ __launch_bounds__(256) void scores_kernel(
    const void* __restrict__ cand,
    const float* __restrict__ W1g, const float* __restrict__ b1g,
    const float* __restrict__ W2g, const float* __restrict__ b2g,
    int K, int nN)
{
    __shared__ float4 s_W1[1024];
    __shared__ float4 s_hq[8][4][16];
    int tid = threadIdx.x;
    int is64 = g_is64;
    for (int i = tid; i < 1024; i += 256) {
        int kp = i >> 5, l = i & 31; int k0 = kp * 2;
        s_W1[i] = make_float4(W1g[k0 * 64 + l], W1g[k0 * 64 + l + 32],
                              W1g[(k0 + 1) * 64 + l], W1g[(k0 + 1) * 64 + l + 32]);
    }
    __syncthreads();
    int wid = tid >> 5, lane = tid & 31;
    float b1l = b1g[lane], b1h = b1g[lane + 32];
    float w2l = W2g[lane], w2h = W2g[lane + 32];
    float b2s = b2g[0];
    float* shf = (float*)&s_hq[wid][0][0];
    int nQ = (K + 3) >> 2;
    int q = blockIdx.x * 8 + wid;
    if (q >= nQ) return;
    int c0 = q << 2;
#pragma unroll
    for (int r = 0; r < 4; r++) {
        if (c0 + r < K) {
            int node = idx_at(cand, c0 + r, is64, nN);
            const float* hr = g_hpA + (size_t)node * 64;   // h3 lives in A
            shf[r * 64 + lane] = hr[lane];
            shf[r * 64 + lane + 32] = hr[lane + 32];
        } else {
            shf[r * 64 + lane] = 0.f;
            shf[r * 64 + lane + 32] = 0.f;
        }
    }
    __syncwarp();
    float tl[4], th[4];
#pragma unroll
    for (int r = 0; r < 4; r++) { tl[r] = b1l; th[r] = b1h; }
#pragma unroll
    for (int kq = 0; kq < 16; ++kq) {
        float4 w0 = s_W1[(2 * kq) * 32 + lane];
        float4 w1 = s_W1[(2 * kq + 1) * 32 + lane];
#pragma unroll
        for (int r = 0; r < 4; r++) {
            float4 hv = s_hq[wid][r][kq];
            tl[r] += hv.x * w0.x + hv.y * w0.z + hv.z * w1.x + hv.w * w1.z;
            th[r] += hv.x * w0.y + hv.y * w0.w + hv.z * w1.y + hv.w * w1.w;
        }
    }
#pragma unroll
    for (int r = 0; r < 4; r++) {
        float s = leaky(tl[r]) * w2l + leaky(th[r]) * w2h;
        s = wsum(s) + b2s;
        if (lane == 0 && c0 + r < K) g_scores[c0 + r] = s;
    }
}

// ---- tail: block 0 = softmax; blocks 1.. = cleanup; last-done block resets scalars ----
__global__ __launch_bounds__(256) void tail_kernel(float* __restrict__ out, int K) {
    int tid = threadIdx.x;
    int n0 = g_nl[0];
    if (blockIdx.x == 0) {
        __shared__ float s_red[256];
        float m = -3.4e38f;
        for (int i = tid; i < K; i += 256) m = fmaxf(m, g_scores[i]);
        s_red[tid] = m; __syncthreads();
        for (int o = 128; o; o >>= 1) { if (tid < o) s_red[tid] = fmaxf(s_red[tid], s_red[tid + o]); __syncthreads(); }
        m = s_red[0];
        __syncthreads();
        float sum = 0.f;
        for (int i = tid; i < K; i += 256) sum += expf(g_scores[i] - m);
        s_red[tid] = sum; __syncthreads();
        for (int o = 128; o; o >>= 1) { if (tid < o) s_red[tid] += s_red[tid + o]; __syncthreads(); }
        float invT = 1.f / s_red[0];
        for (int i = tid; i < K; i += 256) out[i] = expf(g_scores[i] - m) * invT;
    } else {
        int nb = gridDim.x - 1;
        int stride = nb * blockDim.x;
        for (int i = (blockIdx.x - 1) * blockDim.x + tid; i < n0; i += stride) {
            g_stamp[g_list[i]] = 0;
            g_cntlv[i] = 0;
            g_cntlv[LCAP + i] = 0;
            g_cntlv[2 * LCAP + i] = 0;
        }
    }
    __syncthreads();
    if (tid == 0) {
        __threadfence();
        int d = atomicAdd(&g_done, 1);
        if (d == (int)gridDim.x - 1) {
            g_done = 0;
            g_nlist = 0;
            g_ecnt[0] = g_ecnt[1] = g_ecnt[2] = 0;
            g_nl[0] = g_nl[1] = g_nl[2] = g_nl[3] = 0;
        }
    }
}

// ---------------- launch ----------------
extern "C" void kernel_launch(void* const* d_in, const int* in_sizes, int n_in,
                              void* d_out, int out_size) {
    const float* x     = (const float*)d_in[0];
    const void*  ei    = d_in[1];
    const void*  cand  = d_in[2];
    const float* pW    = (const float*)d_in[3];
    const float* pb    = (const float*)d_in[4];
    const float* eW    = (const float*)d_in[5];
    const float* eb    = (const float*)d_in[6];
    const float* gamma = (const float*)d_in[7];
    const float* beta  = (const float*)d_in[8];
    const float* sW1   = (const float*)d_in[9];
    const float* sb1   = (const float*)d_in[10];
    const float* sW2   = (const float*)d_in[11];
    const float* sb2   = (const float*)d_in[12];
    const float* hW1   = (const float*)d_in[13];
    const float* hb1   = (const float*)d_in[14];
    const float* hW2   = (const float*)d_in[15];
    const float* hb2   = (const float*)d_in[16];

    int nN = in_sizes[0] / FIN;
    int E  = in_sizes[1] / 2;
    int K  = in_sizes[2];
    int pBlocks = (E + 2047) / 2048;   // 8 edges/thread, 256 threads

    mark_cands_kernel<<<1, 512>>>((const unsigned*)ei, cand, E, K, nN);   // 1
    pass3_kernel<<<pBlocks, 256>>>(ei, E, nN);                            // 2
    passc_kernel<<<pBlocks, 256>>>(ei, E, nN, 2);                         // 3
    passc_kernel<<<pBlocks, 256>>>(ei, E, nN, 1);                         // 4 <- profiled
    embed_list_kernel<<<128, 128>>>(x, pW, pb, eW, eb, gamma, beta, nN);  // 5
    mp_fused_kernel<<<64, 256>>>(sW1, sb1, sW2, sb2);                     // 6

    int sBlocks = ((K + 3) / 4 + 7) / 8;
    scores_kernel<<<sBlocks, 256>>>(cand, hW1, hb1, hW2, hb2, K, nN);     // 7
    tail_kernel<<<16, 256>>>((float*)d_out, K);                           // 8
}